// round 8
// baseline (speedup 1.0000x reference)
#include <cuda_runtime.h>
#include <cstdint>

#define NBLK 16
#define NTHR 352                 // 11 warps: 3 cosine + 8 count
#define CNT_WARPS 8
#define CNT_THREADS (CNT_WARPS * 32)   // 256

// Packed: fixed-point partial-loss sum bits[0:44), done count bits[44:64).
// Zero at module load; last-arriving block resets -> graph-replay safe.
__device__ unsigned long long g_acc = 0ull;

#define DONE_ONE (1ull << 44)
#define LOW44 ((1ull << 44) - 1ull)
#define FIX_SCALE 4194304.0f     // 2^22; max total 2*65536*2^22 = 2^39 < 2^44

__global__ void __launch_bounds__(NTHR, 1)
fused_kernel(const float* __restrict__ t1,
             const float* __restrict__ t2,
             const int* __restrict__ labels,
             int n, int d,
             float* __restrict__ out) {
    const int wid = threadIdx.x >> 5;
    const int lane = threadIdx.x & 31;

    __shared__ float s_cos[3];
    __shared__ int s0[CNT_WARPS], s1[CNT_WARPS], s2[CNT_WARPS];

    if (wid < 3) {
        // Cosine warps: labels are in {0,1,2} and the reference gathers rows
        // BY LABEL VALUE, so only rows 0..2 of t1/t2 matter. Computed
        // redundantly in every block (L2-broadcast, hidden under label loads)
        // so no block ever waits on another block's cosine.
        const float4* a = (const float4*)(t1 + (size_t)wid * d);
        const float4* b = (const float4*)(t2 + (size_t)wid * d);
        const int d4 = d >> 2;               // 128
        float dot = 0.f, na = 0.f, nbb = 0.f;
        #pragma unroll 4
        for (int i = lane; i < d4; i += 32) {
            float4 x = a[i], y = b[i];
            dot += x.x * y.x + x.y * y.y + x.z * y.z + x.w * y.w;
            na  += x.x * x.x + x.y * x.y + x.z * x.z + x.w * x.w;
            nbb += y.x * y.x + y.y * y.y + y.z * y.z + y.w * y.w;
        }
        #pragma unroll
        for (int off = 16; off > 0; off >>= 1) {
            dot += __shfl_down_sync(0xffffffffu, dot, off);
            na  += __shfl_down_sync(0xffffffffu, na, off);
            nbb += __shfl_down_sync(0xffffffffu, nbb, off);
        }
        if (lane == 0) {
            float denom = fmaxf(sqrtf(na) * sqrtf(nbb), 1e-8f);
            s_cos[wid] = dot / denom;
        }
    } else {
        // Count warps: this block's 1/NBLK slice of labels.
        // 16 blocks x 256 count-threads x 4 int4 = 65536 labels.
        const int ct = threadIdx.x - 96;     // 0..255
        const int n4 = n >> 2;
        const int stride = NBLK * CNT_THREADS;
        int c0 = 0, c1 = 0, c2 = 0;
        const int4* l4 = (const int4*)labels;
        #pragma unroll 4
        for (int i = blockIdx.x * CNT_THREADS + ct; i < n4; i += stride) {
            int4 v = l4[i];
            c0 += __popc(__ballot_sync(0xffffffffu, v.x == 0))
                + __popc(__ballot_sync(0xffffffffu, v.y == 0))
                + __popc(__ballot_sync(0xffffffffu, v.z == 0))
                + __popc(__ballot_sync(0xffffffffu, v.w == 0));
            c1 += __popc(__ballot_sync(0xffffffffu, v.x == 1))
                + __popc(__ballot_sync(0xffffffffu, v.y == 1))
                + __popc(__ballot_sync(0xffffffffu, v.z == 1))
                + __popc(__ballot_sync(0xffffffffu, v.w == 1));
            c2 += __popc(__ballot_sync(0xffffffffu, v.x == 2))
                + __popc(__ballot_sync(0xffffffffu, v.y == 2))
                + __popc(__ballot_sync(0xffffffffu, v.z == 2))
                + __popc(__ballot_sync(0xffffffffu, v.w == 2));
        }
        if (blockIdx.x == 0) {               // warp-synchronous tail (n % 4)
            const int base = n4 << 2;
            const int cwid = wid - 3;
            for (int i0 = base + (cwid << 5); i0 < n; i0 += CNT_THREADS) {
                int i = i0 + lane;
                int l = (i < n) ? labels[i] : -1;
                c0 += __popc(__ballot_sync(0xffffffffu, l == 0));
                c1 += __popc(__ballot_sync(0xffffffffu, l == 1));
                c2 += __popc(__ballot_sync(0xffffffffu, l == 2));
            }
        }
        if (lane == 0) {                     // ballot sums are warp-uniform
            s0[wid - 3] = c0;
            s1[wid - 3] = c1;
            s2[wid - 3] = c2;
        }
    }
    __syncthreads();

    if (threadIdx.x == 0) {
        int c0 = 0, c1 = 0, c2 = 0;
        #pragma unroll
        for (int w = 0; w < CNT_WARPS; ++w) { c0 += s0[w]; c1 += s1[w]; c2 += s2[w]; }
        // Partial loss for this block's label slice (all terms >= 0).
        float partial = (float)c0 * (1.0f - s_cos[0])
                      + (float)c2 * (1.0f - s_cos[2])
                      + (float)c1 * fabsf(s_cos[1]);
        unsigned long long contrib =
            (unsigned long long)(partial * FIX_SCALE) | DONE_ONE;
        unsigned long long old = atomicAdd(&g_acc, contrib);
        unsigned long long total = old + contrib;
        if ((total >> 44) == (unsigned long long)NBLK) {
            // Last block: atomic return carries the complete sum. No poll,
            // no extra global read.
            out[0] = (float)(double)(total & LOW44)
                     * (1.0f / FIX_SCALE) / (float)n;
            // Reset for next graph replay (all arrivals already happened).
            *(volatile unsigned long long*)&g_acc = 0ull;
        }
    }
}

extern "C" void kernel_launch(void* const* d_in, const int* in_sizes, int n_in,
                              void* d_out, int out_size) {
    const float* t1 = (const float*)d_in[0];
    const float* t2 = (const float*)d_in[1];
    const int* labels = (const int*)d_in[2];
    float* out = (float*)d_out;

    int n = in_sizes[2];          // 65536 labels
    int d = in_sizes[0] / n;      // 512

    fused_kernel<<<NBLK, NTHR>>>(t1, t2, labels, n, d, out);
}

// round 9
// speedup vs baseline: 1.0049x; 1.0049x over previous
#include <cuda_runtime.h>
#include <cstdint>

#define NBLK 16
#define NTHR 352                       // 11 warps: 3 cosine + 8 count
#define CNT_WARPS 8
#define CNT_THREADS (CNT_WARPS * 32)   // 256

// Packed: c0 bits[0:20), c2 bits[20:40), done bits[40:64).
// Zero at module load; last-arriving block resets -> graph-replay safe.
__device__ unsigned long long g_acc = 0ull;

#define DONE_ONE (1ull << 40)

__global__ void __launch_bounds__(NTHR, 1)
fused_kernel(const float* __restrict__ t1,
             const float* __restrict__ t2,
             const int* __restrict__ labels,
             int n, int d,
             float* __restrict__ out) {
    const int wid = threadIdx.x >> 5;
    const int lane = threadIdx.x & 31;

    __shared__ float s_cos[3];
    __shared__ int s0[CNT_WARPS], s2[CNT_WARPS];
    __shared__ int s_last;                       // 1 iff this block arrived last
    __shared__ unsigned long long s_total;       // packed totals (valid if s_last)

    if (wid < 3) {
        // Cosine warps: labels in {0,1,2}; the reference gathers rows BY
        // LABEL VALUE, so only rows 0..2 of t1/t2 matter. Computed
        // redundantly in every block so the last-arriving block can finalize
        // with ITS OWN cosines -- no cross-block cosine dependency.
        const float4* a = (const float4*)(t1 + (size_t)wid * d);
        const float4* b = (const float4*)(t2 + (size_t)wid * d);
        const int d4 = d >> 2;                   // 128
        float dot = 0.f, na = 0.f, nbb = 0.f;
        #pragma unroll 4
        for (int i = lane; i < d4; i += 32) {
            float4 x = a[i], y = b[i];
            dot += x.x * y.x + x.y * y.y + x.z * y.z + x.w * y.w;
            na  += x.x * x.x + x.y * x.y + x.z * x.z + x.w * x.w;
            nbb += y.x * y.x + y.y * y.y + y.z * y.z + y.w * y.w;
        }
        #pragma unroll
        for (int off = 16; off > 0; off >>= 1) {
            dot += __shfl_down_sync(0xffffffffu, dot, off);
            na  += __shfl_down_sync(0xffffffffu, na, off);
            nbb += __shfl_down_sync(0xffffffffu, nbb, off);
        }
        if (lane == 0) {
            float denom = fmaxf(sqrtf(na) * sqrtf(nbb), 1e-8f);
            s_cos[wid] = dot / denom;
        }
    } else {
        // Count warps: this block's 1/NBLK slice. Only c0 and c2 are counted;
        // c1 = n - c0 - c2 globally at the end.
        const int ct = threadIdx.x - 96;         // 0..255
        const int n4 = n >> 2;
        const int stride = NBLK * CNT_THREADS;
        int c0 = 0, c2 = 0;
        const int4* l4 = (const int4*)labels;
        #pragma unroll 4
        for (int i = blockIdx.x * CNT_THREADS + ct; i < n4; i += stride) {
            int4 v = l4[i];
            c0 += __popc(__ballot_sync(0xffffffffu, v.x == 0))
                + __popc(__ballot_sync(0xffffffffu, v.y == 0))
                + __popc(__ballot_sync(0xffffffffu, v.z == 0))
                + __popc(__ballot_sync(0xffffffffu, v.w == 0));
            c2 += __popc(__ballot_sync(0xffffffffu, v.x == 2))
                + __popc(__ballot_sync(0xffffffffu, v.y == 2))
                + __popc(__ballot_sync(0xffffffffu, v.z == 2))
                + __popc(__ballot_sync(0xffffffffu, v.w == 2));
        }
        if (blockIdx.x == 0) {                   // warp-synchronous tail (n%4)
            const int base = n4 << 2;
            const int cwid = wid - 3;
            for (int i0 = base + (cwid << 5); i0 < n; i0 += CNT_THREADS) {
                int i = i0 + lane;
                int l = (i < n) ? labels[i] : -1;
                c0 += __popc(__ballot_sync(0xffffffffu, l == 0));
                c2 += __popc(__ballot_sync(0xffffffffu, l == 2));
            }
        }
        if (lane == 0) {                         // ballot sums are warp-uniform
            s0[wid - 3] = c0;
            s2[wid - 3] = c2;
        }
        // Count warps only: reduce + post the atomic NOW, overlapping its
        // ~320cy round-trip with the cosine warps' FMA/shfl/sqrt work.
        asm volatile("bar.sync 1, %0;" :: "r"(CNT_THREADS) : "memory");
        if (threadIdx.x == 96) {
            int t0 = 0, t2v = 0;
            #pragma unroll
            for (int w = 0; w < CNT_WARPS; ++w) { t0 += s0[w]; t2v += s2[w]; }
            unsigned long long contrib = (unsigned long long)t0
                                       | ((unsigned long long)t2v << 20)
                                       | DONE_ONE;
            unsigned long long total = atomicAdd(&g_acc, contrib) + contrib;
            int last = ((total >> 40) == (unsigned long long)NBLK);
            s_last = last;
            s_total = total;
        }
    }
    __syncthreads();

    if (threadIdx.x == 0 && s_last) {
        // Last-arriving block finalizes with its own cosines.
        unsigned long long total = s_total;
        int c0 = (int)(total & 0xFFFFFull);
        int c2 = (int)((total >> 20) & 0xFFFFFull);
        int c1 = n - c0 - c2;
        float loss = (float)c0 * (1.0f - s_cos[0])
                   + (float)c2 * (1.0f - s_cos[2])
                   + (float)c1 * fabsf(s_cos[1]);
        out[0] = loss / (float)n;
        // Reset for the next graph replay (all arrivals already happened).
        *(volatile unsigned long long*)&g_acc = 0ull;
    }
}

extern "C" void kernel_launch(void* const* d_in, const int* in_sizes, int n_in,
                              void* d_out, int out_size) {
    const float* t1 = (const float*)d_in[0];
    const float* t2 = (const float*)d_in[1];
    const int* labels = (const int*)d_in[2];
    float* out = (float*)d_out;

    int n = in_sizes[2];          // 65536 labels
    int d = in_sizes[0] / n;      // 512

    fused_kernel<<<NBLK, NTHR>>>(t1, t2, labels, n, d, out);
}